// round 16
// baseline (speedup 1.0000x reference)
#include <cuda_runtime.h>
#include <math.h>

#define NN 50000
#define EE 800000
#define D0 192
#define D1 208
#define BB 64
#define RT 64
#define RS 68
#define AGG 24
#define EPSV 1e-5f
#define NEGINF __int_as_float(0xff800000)
#define POSINF __int_as_float(0x7f800000)

typedef unsigned long long u64;

// ---------------- device scratch ----------------
__device__ __align__(16) float g_agg1[(size_t)NN*AGG];
__device__ __align__(16) float g_agg2[(size_t)NN*AGG];
__device__ float g_sum1[D0], g_sq1[D0], g_s1[D0], g_t1[D0];
__device__ float g_sum2[D1], g_sq2[D1];
__device__ __align__(16) float g_G[59*D1];
__device__ float g_S1[BB*D0], g_Mx1[BB*D0], g_Mn1[BB*D0];
__device__ float g_S2[BB*D1], g_Mx2[BB*D1], g_Mn2[BB*D1];
__device__ float g_Sx[BB*16], g_Mxx[BB*16];
__device__ float g_cnt[BB];
__device__ float g_hidden[BB*624];
__device__ float g_sink;

// ---------------- helpers ----------------
__device__ __forceinline__ void red4(float* addr, float4 v){
    asm volatile("red.global.add.v4.f32 [%0], {%1,%2,%3,%4};"
                 :: "l"(addr), "f"(v.x), "f"(v.y), "f"(v.z), "f"(v.w) : "memory");
}
__device__ __forceinline__ void atomicMaxF(float* a, float v){
    if (v >= 0.0f) atomicMax((int*)a, __float_as_int(v));
    else           atomicMin((unsigned int*)a, __float_as_uint(v));
}
__device__ __forceinline__ void atomicMinF(float* a, float v){
    if (v >= 0.0f) atomicMin((int*)a, __float_as_int(v));
    else           atomicMax((unsigned int*)a, __float_as_uint(v));
}
__device__ __forceinline__ u64 pack2(float a, float b){
    u64 r; asm("mov.b64 %0, {%1, %2};" : "=l"(r) : "f"(a), "f"(b)); return r;
}
__device__ __forceinline__ void unpack2(u64 v, float& a, float& b){
    asm("mov.b64 {%0, %1}, %2;" : "=f"(a), "=f"(b) : "l"(v));
}
__device__ __forceinline__ u64 fma2(u64 a, u64 b, u64 c){
    u64 d; asm("fma.rn.f32x2 %0, %1, %2, %3;" : "=l"(d) : "l"(a), "l"(b), "l"(c)); return d;
}
__device__ __forceinline__ u64 add2(u64 a, u64 b){
    u64 d; asm("add.rn.f32x2 %0, %1, %2;" : "=l"(d) : "l"(a), "l"(b)); return d;
}

// ---------------- kernels ----------------
// zeroA: only agg1 (gates edge1)
__global__ void k_zeroA(){
    int tid = blockIdx.x*blockDim.x + threadIdx.x;
    int st  = gridDim.x*blockDim.x;
    for (int i=tid;i<NN*AGG;i+=st) g_agg1[i]=0.f;
}

// zeroB: stats/pool accumulators (stream 2; joined before pre1)
__global__ void k_zeroB(){
    int tid = blockIdx.x*blockDim.x + threadIdx.x;
    int st  = gridDim.x*blockDim.x;
    for (int i=tid;i<BB*D0;i+=st){ g_S1[i]=0.f; g_Mx1[i]=NEGINF; g_Mn1[i]=POSINF; }
    for (int i=tid;i<BB*D1;i+=st){ g_S2[i]=0.f; g_Mx2[i]=NEGINF; g_Mn2[i]=POSINF; }
    for (int i=tid;i<BB*16;i+=st){ g_Sx[i]=0.f; g_Mxx[i]=NEGINF; }
    if (tid < D0){ g_sum1[tid]=0.f; g_sq1[tid]=0.f; }
    if (tid < D1){ g_sum2[tid]=0.f; g_sq2[tid]=0.f; }
    if (tid < BB) g_cnt[tid]=0.f;
}

// zero2: agg2 (stream 2, before edge2)
__global__ void k_zero2(){
    int tid = blockIdx.x*blockDim.x + threadIdx.x;
    int st  = gridDim.x*blockDim.x;
    for (int i=tid;i<NN*AGG;i+=st) g_agg2[i]=0.f;
}

__global__ void k_prefetch(const float* __restrict__ Wl1){
    int tid = blockIdx.x*blockDim.x + threadIdx.x;
    int st  = gridDim.x*blockDim.x;
    float s = 0.f;
    for (int i=tid; i<1248*624; i+=st) s += __ldg(&Wl1[i]);
    if (s == 1.23456789e30f) g_sink = s;
}

__global__ void k_edge1(const int* __restrict__ src, const int* __restrict__ dst,
                        const float* __restrict__ ea, const float* __restrict__ x){
    int e = blockIdx.x*blockDim.x + threadIdx.x;
    if (e >= EE) return;
    int s = src[e], d = dst[e];
    const float4* xr = (const float4*)(x + (size_t)s*16);
    float4 v0=xr[0], v1=xr[1], v2=xr[2], v3=xr[3];
    float* base = g_agg1 + (size_t)d*AGG;
    red4(base,    v0); red4(base+4,  v1); red4(base+8,  v2); red4(base+12, v3);
    float4 a = ((const float4*)ea)[e];
    red4(base+16, a);
    atomicAdd(base+20, 1.0f);
}

__global__ void k_edge2(const int* __restrict__ src, const int* __restrict__ dst){
    int e = blockIdx.x*blockDim.x + threadIdx.x;
    if (e >= EE) return;
    int s = src[e], d = dst[e];
    const float4* sb = (const float4*)(g_agg1 + (size_t)s*AGG);
    float4 v0=sb[0], v1=sb[1], v2=sb[2], v3=sb[3], a=sb[4];
    float dg = g_agg1[(size_t)s*AGG+20];
    float* db = g_agg2 + (size_t)d*AGG;
    red4(db,    v0); red4(db+4,  v1); red4(db+8,  v2); red4(db+12, v3);
    red4(db+16, a);
    atomicAdd(db+20, dg);
}

// h1_pre GEMM + BN1 stats + pooling; f32x2 packed math, 16 rows/group
__global__ __launch_bounds__(192) void k_pre1(
        const float* __restrict__ Wm1, const float* __restrict__ bm1,
        const float* __restrict__ We1, const float* __restrict__ be1b,
        const float* __restrict__ Ws1, const float* __restrict__ bs1,
        const float* __restrict__ x, const int* __restrict__ batch){
    __shared__ __align__(16) float fsm[37*RS];
    __shared__ int sbat[RT];
    int c = threadIdx.x;
    float w[37];
    #pragma unroll
    for (int k=0;k<16;k++) w[k]    = Wm1[k*D0+c];
    #pragma unroll
    for (int k=0;k<4;k++)  w[16+k] = We1[k*D0+c];
    #pragma unroll
    for (int k=0;k<16;k++) w[20+k] = Ws1[k*D0+c];
    w[36] = bm1[c] + be1b[c];
    float initv = bs1[c];
    int brow = blockIdx.x*RT;
    int nrows = min(RT, NN - brow);
    for (int idx=c; idx<RT*16; idx+=192){
        int r=idx>>4, k=idx&15; bool ok=r<nrows; int row=brow+r;
        fsm[k*RS+r]      = ok ? g_agg1[(size_t)row*AGG+k] : 0.f;
        fsm[(20+k)*RS+r] = ok ? x[(size_t)row*16+k]       : 0.f;
    }
    for (int idx=c; idx<RT*4; idx+=192){
        int r=idx>>2, k=idx&3; bool ok=r<nrows; int row=brow+r;
        fsm[(16+k)*RS+r] = ok ? g_agg1[(size_t)row*AGG+16+k] : 0.f;
    }
    for (int idx=c; idx<RT; idx+=192){
        bool ok=idx<nrows; int row=brow+idx;
        fsm[36*RS+idx] = ok ? g_agg1[(size_t)row*AGG+20] : 0.f;
        sbat[idx] = ok ? batch[row] : -1;
    }
    __syncthreads();
    bool uniform = (sbat[0] == sbat[nrows-1]);
    bool fullblk = uniform && (nrows == RT);
    float lsum=0.f, lsq=0.f;
    u64 lsum2 = pack2(0.f,0.f), lsq2 = lsum2;
    float rsum=0.f, rmx=NEGINF, rmn=POSINF;
    int cur = sbat[0];
    u64 init2 = pack2(initv, initv);
    for (int g16=0; g16<RT/16; ++g16){
        u64 acc[8];
        #pragma unroll
        for (int i=0;i<8;i++) acc[i] = init2;
        const float* fp = fsm + g16*16;
        #pragma unroll
        for (int k=0;k<37;k++){
            const ulonglong2* q = (const ulonglong2*)(fp + k*RS);
            ulonglong2 u0=q[0], u1=q[1], u2=q[2], u3=q[3];
            u64 wk2 = pack2(w[k], w[k]);
            acc[0]=fma2(wk2,u0.x,acc[0]); acc[1]=fma2(wk2,u0.y,acc[1]);
            acc[2]=fma2(wk2,u1.x,acc[2]); acc[3]=fma2(wk2,u1.y,acc[3]);
            acc[4]=fma2(wk2,u2.x,acc[4]); acc[5]=fma2(wk2,u2.y,acc[5]);
            acc[6]=fma2(wk2,u3.x,acc[6]); acc[7]=fma2(wk2,u3.y,acc[7]);
        }
        if (fullblk){
            #pragma unroll
            for (int i=0;i<8;i++){
                lsum2 = add2(lsum2, acc[i]);
                lsq2  = fma2(acc[i], acc[i], lsq2);
                float a,b; unpack2(acc[i], a, b);
                rmx = fmaxf(rmx, fmaxf(a,b));
                rmn = fminf(rmn, fminf(a,b));
            }
        } else {
            float vals[16];
            #pragma unroll
            for (int i=0;i<8;i++) unpack2(acc[i], vals[2*i], vals[2*i+1]);
            int rb = g16*16;
            #pragma unroll
            for (int q2=0;q2<16;q2++){
                int r = rb+q2;
                if (r < nrows){
                    float v = vals[q2];
                    lsum += v; lsq = fmaf(v,v,lsq);
                    int b = sbat[r];
                    if (b != cur){
                        atomicAdd(&g_S1[cur*D0+c], rsum);
                        atomicMaxF(&g_Mx1[cur*D0+c], rmx);
                        atomicMinF(&g_Mn1[cur*D0+c], rmn);
                        rsum=0.f; rmx=NEGINF; rmn=POSINF; cur=b;
                    }
                    rsum += v; rmx = fmaxf(rmx,v); rmn = fminf(rmn,v);
                }
            }
        }
    }
    {
        float sa, sb;
        unpack2(lsum2, sa, sb); lsum += sa + sb;
        unpack2(lsq2,  sa, sb); lsq  += sa + sb;
    }
    atomicAdd(&g_S1[cur*D0+c], fullblk ? lsum : rsum);
    atomicMaxF(&g_Mx1[cur*D0+c], rmx);
    atomicMinF(&g_Mn1[cur*D0+c], rmn);
    atomicAdd(&g_sum1[c], lsum);
    atomicAdd(&g_sq1[c],  lsq);
    if (c < 16){
        if (fullblk){
            // parallel (unrolled) sum/max, no run-scan
            float xs=0.f, xmx=NEGINF;
            const float* xr = fsm + (20+c)*RS;
            #pragma unroll
            for (int r=0;r<RT;r+=4){
                float a0=xr[r], a1=xr[r+1], a2=xr[r+2], a3=xr[r+3];
                xs += (a0+a1)+(a2+a3);
                xmx = fmaxf(xmx, fmaxf(fmaxf(a0,a1), fmaxf(a2,a3)));
            }
            int b0 = sbat[0];
            atomicAdd(&g_Sx[b0*16+c], xs);
            atomicMaxF(&g_Mxx[b0*16+c], xmx);
            if (c==0) atomicAdd(&g_cnt[b0], (float)RT);
        } else {
            float xs=0.f, xmx=NEGINF, rc=0.f;
            int cur2 = sbat[0];
            for (int r=0;r<nrows;r++){
                int b = sbat[r];
                if (b != cur2){
                    atomicAdd(&g_Sx[cur2*16+c], xs);
                    atomicMaxF(&g_Mxx[cur2*16+c], xmx);
                    if (c==0) atomicAdd(&g_cnt[cur2], rc);
                    xs=0.f; xmx=NEGINF; rc=0.f; cur2=b;
                }
                float xv = fsm[(20+c)*RS+r];
                xs += xv; xmx = fmaxf(xmx,xv); rc += 1.f;
            }
            atomicAdd(&g_Sx[cur2*16+c], xs);
            atomicMaxF(&g_Mxx[cur2*16+c], xmx);
            if (c==0) atomicAdd(&g_cnt[cur2], rc);
        }
    }
}

// composeG with folded BN1 stats; 4-way ILP on the 192-deep chains
__global__ __launch_bounds__(D1) void k_composeG(
        const float* __restrict__ g1, const float* __restrict__ be1,
        const float* __restrict__ Wm1, const float* __restrict__ We1,
        const float* __restrict__ Ws1, const float* __restrict__ bm1,
        const float* __restrict__ be1b, const float* __restrict__ bs1,
        const float* __restrict__ Wm2, const float* __restrict__ We2,
        const float* __restrict__ bm2, const float* __restrict__ be2b){
    __shared__ float s1s[D0], t1s[D0];
    int c = threadIdx.x;
    int f = blockIdx.x;
    if (c < D0){
        float m = g_sum1[c]*(1.0f/NN);
        float v = g_sq1[c]*(1.0f/NN) - m*m;
        float s = g1[c]*rsqrtf(v+EPSV);
        float t = be1[c] - m*s;
        s1s[c] = s; t1s[c] = t;
        if (f == 0){ g_s1[c] = s; g_t1[c] = t; }
    }
    __syncthreads();
    float acc = 0.f;
    if (f < 36){
        const float* wr;
        if (f < 16)      wr = Wm1 + f*D0;
        else if (f < 20) wr = We1 + (f-16)*D0;
        else             wr = Ws1 + (f-20)*D0;
        float a0=0.f, a1=0.f, a2=0.f, a3=0.f;
        #pragma unroll 4
        for (int j=0;j<D0;j+=4){
            a0 = fmaf(wr[j]  *s1s[j],   Wm2[(j)*D1+c],   a0);
            a1 = fmaf(wr[j+1]*s1s[j+1], Wm2[(j+1)*D1+c], a1);
            a2 = fmaf(wr[j+2]*s1s[j+2], Wm2[(j+2)*D1+c], a2);
            a3 = fmaf(wr[j+3]*s1s[j+3], Wm2[(j+3)*D1+c], a3);
        }
        acc = (a0+a1)+(a2+a3);
        if (f >= 20){
            int k = f-20;
            acc += Wm2[(D0+k)*D1+c];
            if (c < D0) acc += Wm1[k*D0+c]*s1s[c];
        }
    } else if (f < 40){
        int k = f-36;
        acc = We2[k*D1+c] + ((c<D0) ? We1[k*D0+c]*s1s[c] : 0.f);
    } else if (f < 56){
        int k = f-40;
        acc = (c<D0) ? Ws1[k*D0+c]*s1s[c] : ((c-D0==k) ? 1.f : 0.f);
    } else if (f == 56){
        float a0=0.f, a1=0.f, a2=0.f, a3=0.f;
        #pragma unroll 4
        for (int j=0;j<D0;j+=4){
            a0 = fmaf((bm1[j]  +be1b[j]) *s1s[j],   Wm2[(j)*D1+c],   a0);
            a1 = fmaf((bm1[j+1]+be1b[j+1])*s1s[j+1], Wm2[(j+1)*D1+c], a1);
            a2 = fmaf((bm1[j+2]+be1b[j+2])*s1s[j+2], Wm2[(j+2)*D1+c], a2);
            a3 = fmaf((bm1[j+3]+be1b[j+3])*s1s[j+3], Wm2[(j+3)*D1+c], a3);
        }
        acc = (a0+a1)+(a2+a3);
    } else if (f == 57){
        float a0=0.f, a1=0.f, a2=0.f, a3=0.f;
        #pragma unroll 4
        for (int j=0;j<D0;j+=4){
            a0 = fmaf(bs1[j]  *s1s[j]  +t1s[j],   Wm2[(j)*D1+c],   a0);
            a1 = fmaf(bs1[j+1]*s1s[j+1]+t1s[j+1], Wm2[(j+1)*D1+c], a1);
            a2 = fmaf(bs1[j+2]*s1s[j+2]+t1s[j+2], Wm2[(j+2)*D1+c], a2);
            a3 = fmaf(bs1[j+3]*s1s[j+3]+t1s[j+3], Wm2[(j+3)*D1+c], a3);
        }
        acc = (a0+a1)+(a2+a3);
        acc += bm2[c]+be2b[c];
        if (c < D0) acc += (bm1[c]+be1b[c])*s1s[c];
    } else {
        acc = (c<D0) ? bs1[c]*s1s[c]+t1s[c] : 0.f;
    }
    g_G[f*D1+c] = acc;
}

// h2_pre = F @ G + BN2 stats + pooling; 208 threads, row-58 fold
__global__ __launch_bounds__(208) void k_h2(const float* __restrict__ x,
                                            const int* __restrict__ batch){
    __shared__ __align__(16) float fsm[58*RS];
    __shared__ int sbat[RT];
    int c = threadIdx.x;
    int brow = blockIdx.x*RT;
    int nrows = min(RT, NN - brow);
    for (int idx=c; idx<RT*16; idx+=208){
        int r=idx>>4, k=idx&15; bool ok=r<nrows; int row=brow+r;
        fsm[k*RS+r]      = ok ? g_agg2[(size_t)row*AGG+k] : 0.f;
        fsm[(20+k)*RS+r] = ok ? g_agg1[(size_t)row*AGG+k] : 0.f;
        fsm[(40+k)*RS+r] = ok ? x     [(size_t)row*16+k]  : 0.f;
    }
    for (int idx=c; idx<RT*4; idx+=208){
        int r=idx>>2, k=idx&3; bool ok=r<nrows; int row=brow+r;
        fsm[(16+k)*RS+r] = ok ? g_agg2[(size_t)row*AGG+16+k] : 0.f;
        fsm[(36+k)*RS+r] = ok ? g_agg1[(size_t)row*AGG+16+k] : 0.f;
    }
    for (int idx=c; idx<RT; idx+=208){
        bool ok=idx<nrows; int row=brow+idx;
        fsm[56*RS+idx] = ok ? g_agg2[(size_t)row*AGG+20] : 0.f;
        fsm[57*RS+idx] = ok ? g_agg1[(size_t)row*AGG+20] : 0.f;
        sbat[idx] = ok ? batch[row] : -1;
    }
    __syncthreads();
    bool uniform = (sbat[0] == sbat[nrows-1]);
    bool fullblk = uniform && (nrows == RT);
    float lsum=0.f, lsq=0.f;
    u64 lsum2 = pack2(0.f,0.f), lsq2 = lsum2;
    float rsum=0.f, rmx=NEGINF, rmn=POSINF;
    int cur = sbat[0];
    float g58 = __ldg(&g_G[58*D1+c]);
    u64 init2 = pack2(g58, g58);
    for (int g16=0; g16<RT/16; ++g16){
        u64 acc[8];
        #pragma unroll
        for (int i=0;i<8;i++) acc[i] = init2;
        const float* fp = fsm + g16*16;
        #pragma unroll
        for (int k=0;k<58;k++){
            const ulonglong2* q = (const ulonglong2*)(fp + k*RS);
            ulonglong2 u0=q[0], u1=q[1], u2=q[2], u3=q[3];
            float wk = __ldg(&g_G[k*D1+c]);
            u64 wk2 = pack2(wk, wk);
            acc[0]=fma2(wk2,u0.x,acc[0]); acc[1]=fma2(wk2,u0.y,acc[1]);
            acc[2]=fma2(wk2,u1.x,acc[2]); acc[3]=fma2(wk2,u1.y,acc[3]);
            acc[4]=fma2(wk2,u2.x,acc[4]); acc[5]=fma2(wk2,u2.y,acc[5]);
            acc[6]=fma2(wk2,u3.x,acc[6]); acc[7]=fma2(wk2,u3.y,acc[7]);
        }
        if (fullblk){
            #pragma unroll
            for (int i=0;i<8;i++){
                lsum2 = add2(lsum2, acc[i]);
                lsq2  = fma2(acc[i], acc[i], lsq2);
                float a,b; unpack2(acc[i], a, b);
                rmx = fmaxf(rmx, fmaxf(a,b));
                rmn = fminf(rmn, fminf(a,b));
            }
        } else {
            float vals[16];
            #pragma unroll
            for (int i=0;i<8;i++) unpack2(acc[i], vals[2*i], vals[2*i+1]);
            int rb = g16*16;
            #pragma unroll
            for (int q2=0;q2<16;q2++){
                int r = rb+q2;
                if (r < nrows){
                    float v = vals[q2];
                    lsum += v; lsq = fmaf(v,v,lsq);
                    int b = sbat[r];
                    if (b != cur){
                        atomicAdd(&g_S2[cur*D1+c], rsum);
                        atomicMaxF(&g_Mx2[cur*D1+c], rmx);
                        atomicMinF(&g_Mn2[cur*D1+c], rmn);
                        rsum=0.f; rmx=NEGINF; rmn=POSINF; cur=b;
                    }
                    rsum += v; rmx = fmaxf(rmx,v); rmn = fminf(rmn,v);
                }
            }
        }
    }
    {
        float sa, sb;
        unpack2(lsum2, sa, sb); lsum += sa + sb;
        unpack2(lsq2,  sa, sb); lsq  += sa + sb;
    }
    atomicAdd(&g_S2[cur*D1+c], fullblk ? lsum : rsum);
    atomicMaxF(&g_Mx2[cur*D1+c], rmx);
    atomicMinF(&g_Mn2[cur*D1+c], rmn);
    atomicAdd(&g_sum2[c], lsum);
    atomicAdd(&g_sq2[c],  lsq);
}

// head1 = assemble (BN2 affine + pool compose, in smem) + Linear1 + PReLU
__global__ __launch_bounds__(384) void k_head1(const float* __restrict__ Wl1,
                                               const float* __restrict__ bl1,
                                               const float* __restrict__ alpha,
                                               const float* __restrict__ g2,
                                               const float* __restrict__ be2){
    extern __shared__ float sp[];   // 16*1252 floats
    __shared__ float s2s[D1], t2s[D1];
    int jc = blockIdx.x % 13, bg = blockIdx.x / 13;   // grid 52
    int t = threadIdx.x;
    for (int c=t; c<D1; c+=384){
        float m = g_sum2[c]*(1.0f/NN);
        float v = g_sq2[c]*(1.0f/NN) - m*m;
        float s = g2[c]*rsqrtf(v+EPSV);
        s2s[c] = s; t2s[c] = be2[c] - m*s;
    }
    __syncthreads();
    for (int idx=t; idx<16*416; idx+=384){
        int bb = idx/416, c = idx%416;
        int b = bg*16+bb;
        float cnt = g_cnt[b];
        float cntc = fmaxf(cnt, 1.f);
        float S, Mx, Mn, s, tt;
        if (c < D1){
            S = g_S2[b*D1+c]; Mx = g_Mx2[b*D1+c]; Mn = g_Mn2[b*D1+c];
            s = s2s[c]; tt = t2s[c];
        } else if (c < 400){
            int k = c - D1;
            S = g_S1[b*D0+k]; Mx = g_Mx1[b*D0+k]; Mn = g_Mn1[b*D0+k];
            s = g_s1[k]; tt = g_t1[k];
        } else {
            int k = c - 400;
            S = g_Sx[b*16+k]; Mx = g_Mxx[b*16+k]; Mn = 0.f;
            s = 1.f; tt = 0.f;
        }
        float sum = s*S + tt*cnt;
        float mx  = (s >= 0.f) ? s*Mx + tt : s*Mn + tt;
        float* pr = sp + bb*1252;
        pr[c]       = sum;
        pr[416 + c] = mx;
        pr[832 + c] = sum/cntc;
    }
    __syncthreads();
    int tj = t % 48, tb = t / 48;
    int j = jc*48 + tj;
    float acc0 = bl1[j], acc1 = acc0;
    const float* p0 = sp + tb*1252;
    const float* p1 = sp + (tb+8)*1252;
    #pragma unroll 4
    for (int k=0;k<1248;k++){
        float wv = Wl1[k*624+j];
        acc0 = fmaf(p0[k], wv, acc0);
        acc1 = fmaf(p1[k], wv, acc1);
    }
    float a = alpha[0];
    g_hidden[(bg*16+tb)*624 + j]   = (acc0 >= 0.f) ? acc0 : a*acc0;
    g_hidden[(bg*16+tb+8)*624 + j] = (acc1 >= 0.f) ? acc1 : a*acc1;
}

__global__ void k_head2(const float* __restrict__ Wl2, const float* __restrict__ bl2,
                        float* __restrict__ out){
    int b = blockIdx.x, l = threadIdx.x;
    float p0=0.f, p1=0.f;
    for (int k=l; k<624; k+=32){
        float h = g_hidden[b*624+k];
        p0 = fmaf(h, Wl2[k*2],   p0);
        p1 = fmaf(h, Wl2[k*2+1], p1);
    }
    #pragma unroll
    for (int o=16;o;o>>=1){
        p0 += __shfl_down_sync(0xffffffffu, p0, o);
        p1 += __shfl_down_sync(0xffffffffu, p1, o);
    }
    if (l==0){
        float a0 = p0+bl2[0], a1 = p1+bl2[1];
        float m = fmaxf(a0,a1);
        float lse = m + logf(expf(a0-m)+expf(a1-m));
        out[b*2+0] = a0-lse;
        out[b*2+1] = a1-lse;
    }
}

extern "C" void kernel_launch(void* const* d_in, const int* in_sizes, int n_in,
                              void* d_out, int out_size) {
    const float* x    = (const float*)d_in[0];
    const int*   ei   = (const int*)  d_in[1];
    const float* ea   = (const float*)d_in[2];
    const int*   batch= (const int*)  d_in[3];
    const float* Wm1  = (const float*)d_in[4];
    const float* bm1  = (const float*)d_in[5];
    const float* We1  = (const float*)d_in[6];
    const float* be1b = (const float*)d_in[7];
    const float* Ws1  = (const float*)d_in[8];
    const float* bs1  = (const float*)d_in[9];
    const float* g1   = (const float*)d_in[10];
    const float* be1  = (const float*)d_in[11];
    const float* Wm2  = (const float*)d_in[12];
    const float* bm2  = (const float*)d_in[13];
    const float* We2  = (const float*)d_in[14];
    const float* be2b = (const float*)d_in[15];
    const float* g2   = (const float*)d_in[16];
    const float* be2  = (const float*)d_in[17];
    const float* Wl1  = (const float*)d_in[18];
    const float* bl1  = (const float*)d_in[19];
    const float* alpha= (const float*)d_in[20];
    const float* Wl2  = (const float*)d_in[21];
    const float* bl2  = (const float*)d_in[22];
    const int* src = ei;
    const int* dst = ei + EE;
    float* out = (float*)d_out;

    static int init_done = 0;
    static cudaStream_t s2;
    static cudaEvent_t ev0, ev1, ev2, evB;
    if (!init_done){
        cudaFuncSetAttribute(k_head1, cudaFuncAttributeMaxDynamicSharedMemorySize,
                             16*1252*(int)sizeof(float));
        cudaStreamCreateWithFlags(&s2, cudaStreamNonBlocking);
        cudaEventCreateWithFlags(&ev0, cudaEventDisableTiming);
        cudaEventCreateWithFlags(&ev1, cudaEventDisableTiming);
        cudaEventCreateWithFlags(&ev2, cudaEventDisableTiming);
        cudaEventCreateWithFlags(&evB, cudaEventDisableTiming);
        init_done = 1;
    }

    int gnode = (NN + RT - 1)/RT;   // 782
    cudaEventRecord(ev0, 0);
    cudaStreamWaitEvent(s2, ev0, 0);
    k_zero2<<<512, 256, 0, s2>>>();
    k_zeroB<<<256, 256, 0, s2>>>();
    k_prefetch<<<148, 256, 0, s2>>>(Wl1);
    cudaEventRecord(evB, s2);
    k_zeroA<<<512, 256>>>();
    k_edge1<<<(EE+255)/256, 256>>>(src, dst, ea, x);
    cudaEventRecord(ev1, 0);
    cudaStreamWaitEvent(s2, ev1, 0);
    k_edge2<<<(EE+255)/256, 256, 0, s2>>>(src, dst);
    cudaEventRecord(ev2, s2);
    cudaStreamWaitEvent(0, evB, 0);   // pre1 needs stats/pool accumulators zeroed
    k_pre1<<<gnode, 192>>>(Wm1, bm1, We1, be1b, Ws1, bs1, x, batch);
    k_composeG<<<59, D1>>>(g1, be1, Wm1, We1, Ws1, bm1, be1b, bs1, Wm2, We2, bm2, be2b);
    cudaStreamWaitEvent(0, ev2, 0);   // join before k_h2 (needs agg2)
    k_h2<<<gnode, D1>>>(x, batch);
    k_head1<<<52, 384, 16*1252*(int)sizeof(float)>>>(Wl1, bl1, alpha, g2, be2);
    k_head2<<<BB, 32>>>(Wl2, bl2, out);
}

// round 17
// speedup vs baseline: 1.0146x; 1.0146x over previous
#include <cuda_runtime.h>
#include <math.h>

#define NN 50000
#define EE 800000
#define D0 192
#define D1 208
#define BB 64
#define RT 64
#define RS 68
#define AGG 24
#define EPSV 1e-5f
#define NEGINF __int_as_float(0xff800000)
#define POSINF __int_as_float(0x7f800000)

typedef unsigned long long u64;

// ---------------- device scratch ----------------
__device__ __align__(16) float g_agg1[(size_t)NN*AGG];
__device__ __align__(16) float g_agg2[(size_t)NN*AGG];
__device__ float g_sum1[D0], g_sq1[D0], g_s1[D0], g_t1[D0];
__device__ float g_sum2[D1], g_sq2[D1];
__device__ __align__(16) float g_G[59*D1];
__device__ float g_S1[BB*D0], g_Mx1[BB*D0], g_Mn1[BB*D0];
__device__ float g_S2[BB*D1], g_Mx2[BB*D1], g_Mn2[BB*D1];
__device__ float g_Sx[BB*16], g_Mxx[BB*16];
__device__ float g_cnt[BB];
__device__ float g_hidden[BB*624];
__device__ float g_sink;

// ---------------- helpers ----------------
__device__ __forceinline__ void red4(float* addr, float4 v){
    asm volatile("red.global.add.v4.f32 [%0], {%1,%2,%3,%4};"
                 :: "l"(addr), "f"(v.x), "f"(v.y), "f"(v.z), "f"(v.w) : "memory");
}
__device__ __forceinline__ void atomicMaxF(float* a, float v){
    if (v >= 0.0f) atomicMax((int*)a, __float_as_int(v));
    else           atomicMin((unsigned int*)a, __float_as_uint(v));
}
__device__ __forceinline__ void atomicMinF(float* a, float v){
    if (v >= 0.0f) atomicMin((int*)a, __float_as_int(v));
    else           atomicMax((unsigned int*)a, __float_as_uint(v));
}
__device__ __forceinline__ u64 pack2(float a, float b){
    u64 r; asm("mov.b64 %0, {%1, %2};" : "=l"(r) : "f"(a), "f"(b)); return r;
}
__device__ __forceinline__ void unpack2(u64 v, float& a, float& b){
    asm("mov.b64 {%0, %1}, %2;" : "=f"(a), "=f"(b) : "l"(v));
}
__device__ __forceinline__ u64 fma2(u64 a, u64 b, u64 c){
    u64 d; asm("fma.rn.f32x2 %0, %1, %2, %3;" : "=l"(d) : "l"(a), "l"(b), "l"(c)); return d;
}
__device__ __forceinline__ u64 add2(u64 a, u64 b){
    u64 d; asm("add.rn.f32x2 %0, %1, %2;" : "=l"(d) : "l"(a), "l"(b)); return d;
}

// ---------------- kernels ----------------
// zero1: agg1 + stats/pool accumulators (main stream; gates edge1+pre1)
__global__ void k_zero1(){
    int tid = blockIdx.x*blockDim.x + threadIdx.x;
    int st  = gridDim.x*blockDim.x;
    for (int i=tid;i<NN*AGG;i+=st) g_agg1[i]=0.f;
    for (int i=tid;i<BB*D0;i+=st){ g_S1[i]=0.f; g_Mx1[i]=NEGINF; g_Mn1[i]=POSINF; }
    for (int i=tid;i<BB*D1;i+=st){ g_S2[i]=0.f; g_Mx2[i]=NEGINF; g_Mn2[i]=POSINF; }
    for (int i=tid;i<BB*16;i+=st){ g_Sx[i]=0.f; g_Mxx[i]=NEGINF; }
    if (tid < D0){ g_sum1[tid]=0.f; g_sq1[tid]=0.f; }
    if (tid < D1){ g_sum2[tid]=0.f; g_sq2[tid]=0.f; }
    if (tid < BB) g_cnt[tid]=0.f;
}

// zero2: agg2 (stream 2, overlaps edge1)
__global__ void k_zero2(){
    int tid = blockIdx.x*blockDim.x + threadIdx.x;
    int st  = gridDim.x*blockDim.x;
    for (int i=tid;i<NN*AGG;i+=st) g_agg2[i]=0.f;
}

__global__ void k_prefetch(const float* __restrict__ Wl1){
    int tid = blockIdx.x*blockDim.x + threadIdx.x;
    int st  = gridDim.x*blockDim.x;
    float s = 0.f;
    for (int i=tid; i<1248*624; i+=st) s += __ldg(&Wl1[i]);
    if (s == 1.23456789e30f) g_sink = s;
}

__global__ void k_edge1(const int* __restrict__ src, const int* __restrict__ dst,
                        const float* __restrict__ ea, const float* __restrict__ x){
    int e = blockIdx.x*blockDim.x + threadIdx.x;
    if (e >= EE) return;
    int s = src[e], d = dst[e];
    const float4* xr = (const float4*)(x + (size_t)s*16);
    float4 v0=xr[0], v1=xr[1], v2=xr[2], v3=xr[3];
    float* base = g_agg1 + (size_t)d*AGG;
    red4(base,    v0); red4(base+4,  v1); red4(base+8,  v2); red4(base+12, v3);
    float4 a = ((const float4*)ea)[e];
    red4(base+16, a);
    atomicAdd(base+20, 1.0f);
}

__global__ void k_edge2(const int* __restrict__ src, const int* __restrict__ dst){
    int e = blockIdx.x*blockDim.x + threadIdx.x;
    if (e >= EE) return;
    int s = src[e], d = dst[e];
    const float4* sb = (const float4*)(g_agg1 + (size_t)s*AGG);
    float4 v0=sb[0], v1=sb[1], v2=sb[2], v3=sb[3], a=sb[4];
    float dg = g_agg1[(size_t)s*AGG+20];
    float* db = g_agg2 + (size_t)d*AGG;
    red4(db,    v0); red4(db+4,  v1); red4(db+8,  v2); red4(db+12, v3);
    red4(db+16, a);
    atomicAdd(db+20, dg);
}

// h1_pre GEMM + BN1 stats + pooling; f32x2 packed math, 16 rows/group
__global__ __launch_bounds__(192) void k_pre1(
        const float* __restrict__ Wm1, const float* __restrict__ bm1,
        const float* __restrict__ We1, const float* __restrict__ be1b,
        const float* __restrict__ Ws1, const float* __restrict__ bs1,
        const float* __restrict__ x, const int* __restrict__ batch){
    __shared__ __align__(16) float fsm[37*RS];
    __shared__ int sbat[RT];
    int c = threadIdx.x;
    float w[37];
    #pragma unroll
    for (int k=0;k<16;k++) w[k]    = Wm1[k*D0+c];
    #pragma unroll
    for (int k=0;k<4;k++)  w[16+k] = We1[k*D0+c];
    #pragma unroll
    for (int k=0;k<16;k++) w[20+k] = Ws1[k*D0+c];
    w[36] = bm1[c] + be1b[c];
    float initv = bs1[c];
    int brow = blockIdx.x*RT;
    int nrows = min(RT, NN - brow);
    for (int idx=c; idx<RT*16; idx+=192){
        int r=idx>>4, k=idx&15; bool ok=r<nrows; int row=brow+r;
        fsm[k*RS+r]      = ok ? g_agg1[(size_t)row*AGG+k] : 0.f;
        fsm[(20+k)*RS+r] = ok ? x[(size_t)row*16+k]       : 0.f;
    }
    for (int idx=c; idx<RT*4; idx+=192){
        int r=idx>>2, k=idx&3; bool ok=r<nrows; int row=brow+r;
        fsm[(16+k)*RS+r] = ok ? g_agg1[(size_t)row*AGG+16+k] : 0.f;
    }
    for (int idx=c; idx<RT; idx+=192){
        bool ok=idx<nrows; int row=brow+idx;
        fsm[36*RS+idx] = ok ? g_agg1[(size_t)row*AGG+20] : 0.f;
        sbat[idx] = ok ? batch[row] : -1;
    }
    __syncthreads();
    bool uniform = (sbat[0] == sbat[nrows-1]);
    bool fullblk = uniform && (nrows == RT);
    float lsum=0.f, lsq=0.f;
    u64 lsum2 = pack2(0.f,0.f), lsq2 = lsum2;
    float rsum=0.f, rmx=NEGINF, rmn=POSINF;
    int cur = sbat[0];
    u64 init2 = pack2(initv, initv);
    for (int g16=0; g16<RT/16; ++g16){
        u64 acc[8];
        #pragma unroll
        for (int i=0;i<8;i++) acc[i] = init2;
        const float* fp = fsm + g16*16;
        #pragma unroll
        for (int k=0;k<37;k++){
            const ulonglong2* q = (const ulonglong2*)(fp + k*RS);
            ulonglong2 u0=q[0], u1=q[1], u2=q[2], u3=q[3];
            u64 wk2 = pack2(w[k], w[k]);
            acc[0]=fma2(wk2,u0.x,acc[0]); acc[1]=fma2(wk2,u0.y,acc[1]);
            acc[2]=fma2(wk2,u1.x,acc[2]); acc[3]=fma2(wk2,u1.y,acc[3]);
            acc[4]=fma2(wk2,u2.x,acc[4]); acc[5]=fma2(wk2,u2.y,acc[5]);
            acc[6]=fma2(wk2,u3.x,acc[6]); acc[7]=fma2(wk2,u3.y,acc[7]);
        }
        if (fullblk){
            #pragma unroll
            for (int i=0;i<8;i++){
                lsum2 = add2(lsum2, acc[i]);
                lsq2  = fma2(acc[i], acc[i], lsq2);
                float a,b; unpack2(acc[i], a, b);
                rmx = fmaxf(rmx, fmaxf(a,b));
                rmn = fminf(rmn, fminf(a,b));
            }
        } else {
            float vals[16];
            #pragma unroll
            for (int i=0;i<8;i++) unpack2(acc[i], vals[2*i], vals[2*i+1]);
            int rb = g16*16;
            #pragma unroll
            for (int q2=0;q2<16;q2++){
                int r = rb+q2;
                if (r < nrows){
                    float v = vals[q2];
                    lsum += v; lsq = fmaf(v,v,lsq);
                    int b = sbat[r];
                    if (b != cur){
                        atomicAdd(&g_S1[cur*D0+c], rsum);
                        atomicMaxF(&g_Mx1[cur*D0+c], rmx);
                        atomicMinF(&g_Mn1[cur*D0+c], rmn);
                        rsum=0.f; rmx=NEGINF; rmn=POSINF; cur=b;
                    }
                    rsum += v; rmx = fmaxf(rmx,v); rmn = fminf(rmn,v);
                }
            }
        }
    }
    {
        float sa, sb;
        unpack2(lsum2, sa, sb); lsum += sa + sb;
        unpack2(lsq2,  sa, sb); lsq  += sa + sb;
    }
    atomicAdd(&g_S1[cur*D0+c], fullblk ? lsum : rsum);
    atomicMaxF(&g_Mx1[cur*D0+c], rmx);
    atomicMinF(&g_Mn1[cur*D0+c], rmn);
    atomicAdd(&g_sum1[c], lsum);
    atomicAdd(&g_sq1[c],  lsq);
    if (c < 16){
        float xs=0.f, xmx=NEGINF, rc=0.f;
        int cur2 = sbat[0];
        for (int r=0;r<nrows;r++){
            int b = sbat[r];
            if (b != cur2){
                atomicAdd(&g_Sx[cur2*16+c], xs);
                atomicMaxF(&g_Mxx[cur2*16+c], xmx);
                if (c==0) atomicAdd(&g_cnt[cur2], rc);
                xs=0.f; xmx=NEGINF; rc=0.f; cur2=b;
            }
            float xv = fsm[(20+c)*RS+r];
            xs += xv; xmx = fmaxf(xmx,xv); rc += 1.f;
        }
        atomicAdd(&g_Sx[cur2*16+c], xs);
        atomicMaxF(&g_Mxx[cur2*16+c], xmx);
        if (c==0) atomicAdd(&g_cnt[cur2], rc);
    }
}

// composeG with folded BN1 stats; 4-way ILP on the 192-deep chains
__global__ __launch_bounds__(D1) void k_composeG(
        const float* __restrict__ g1, const float* __restrict__ be1,
        const float* __restrict__ Wm1, const float* __restrict__ We1,
        const float* __restrict__ Ws1, const float* __restrict__ bm1,
        const float* __restrict__ be1b, const float* __restrict__ bs1,
        const float* __restrict__ Wm2, const float* __restrict__ We2,
        const float* __restrict__ bm2, const float* __restrict__ be2b){
    __shared__ float s1s[D0], t1s[D0];
    int c = threadIdx.x;
    int f = blockIdx.x;
    if (c < D0){
        float m = g_sum1[c]*(1.0f/NN);
        float v = g_sq1[c]*(1.0f/NN) - m*m;
        float s = g1[c]*rsqrtf(v+EPSV);
        float t = be1[c] - m*s;
        s1s[c] = s; t1s[c] = t;
        if (f == 0){ g_s1[c] = s; g_t1[c] = t; }
    }
    __syncthreads();
    float acc = 0.f;
    if (f < 36){
        const float* wr;
        if (f < 16)      wr = Wm1 + f*D0;
        else if (f < 20) wr = We1 + (f-16)*D0;
        else             wr = Ws1 + (f-20)*D0;
        float a0=0.f, a1=0.f, a2=0.f, a3=0.f;
        #pragma unroll 4
        for (int j=0;j<D0;j+=4){
            a0 = fmaf(wr[j]  *s1s[j],   Wm2[(j)*D1+c],   a0);
            a1 = fmaf(wr[j+1]*s1s[j+1], Wm2[(j+1)*D1+c], a1);
            a2 = fmaf(wr[j+2]*s1s[j+2], Wm2[(j+2)*D1+c], a2);
            a3 = fmaf(wr[j+3]*s1s[j+3], Wm2[(j+3)*D1+c], a3);
        }
        acc = (a0+a1)+(a2+a3);
        if (f >= 20){
            int k = f-20;
            acc += Wm2[(D0+k)*D1+c];
            if (c < D0) acc += Wm1[k*D0+c]*s1s[c];
        }
    } else if (f < 40){
        int k = f-36;
        acc = We2[k*D1+c] + ((c<D0) ? We1[k*D0+c]*s1s[c] : 0.f);
    } else if (f < 56){
        int k = f-40;
        acc = (c<D0) ? Ws1[k*D0+c]*s1s[c] : ((c-D0==k) ? 1.f : 0.f);
    } else if (f == 56){
        float a0=0.f, a1=0.f, a2=0.f, a3=0.f;
        #pragma unroll 4
        for (int j=0;j<D0;j+=4){
            a0 = fmaf((bm1[j]  +be1b[j])  *s1s[j],   Wm2[(j)*D1+c],   a0);
            a1 = fmaf((bm1[j+1]+be1b[j+1])*s1s[j+1], Wm2[(j+1)*D1+c], a1);
            a2 = fmaf((bm1[j+2]+be1b[j+2])*s1s[j+2], Wm2[(j+2)*D1+c], a2);
            a3 = fmaf((bm1[j+3]+be1b[j+3])*s1s[j+3], Wm2[(j+3)*D1+c], a3);
        }
        acc = (a0+a1)+(a2+a3);
    } else if (f == 57){
        float a0=0.f, a1=0.f, a2=0.f, a3=0.f;
        #pragma unroll 4
        for (int j=0;j<D0;j+=4){
            a0 = fmaf(bs1[j]  *s1s[j]  +t1s[j],   Wm2[(j)*D1+c],   a0);
            a1 = fmaf(bs1[j+1]*s1s[j+1]+t1s[j+1], Wm2[(j+1)*D1+c], a1);
            a2 = fmaf(bs1[j+2]*s1s[j+2]+t1s[j+2], Wm2[(j+2)*D1+c], a2);
            a3 = fmaf(bs1[j+3]*s1s[j+3]+t1s[j+3], Wm2[(j+3)*D1+c], a3);
        }
        acc = (a0+a1)+(a2+a3);
        acc += bm2[c]+be2b[c];
        if (c < D0) acc += (bm1[c]+be1b[c])*s1s[c];
    } else {
        acc = (c<D0) ? bs1[c]*s1s[c]+t1s[c] : 0.f;
    }
    g_G[f*D1+c] = acc;
}

// h2_pre = F @ G + BN2 stats + pooling; 208 threads, row-58 fold
__global__ __launch_bounds__(208) void k_h2(const float* __restrict__ x,
                                            const int* __restrict__ batch){
    __shared__ __align__(16) float fsm[58*RS];
    __shared__ int sbat[RT];
    int c = threadIdx.x;
    int brow = blockIdx.x*RT;
    int nrows = min(RT, NN - brow);
    for (int idx=c; idx<RT*16; idx+=208){
        int r=idx>>4, k=idx&15; bool ok=r<nrows; int row=brow+r;
        fsm[k*RS+r]      = ok ? g_agg2[(size_t)row*AGG+k] : 0.f;
        fsm[(20+k)*RS+r] = ok ? g_agg1[(size_t)row*AGG+k] : 0.f;
        fsm[(40+k)*RS+r] = ok ? x     [(size_t)row*16+k]  : 0.f;
    }
    for (int idx=c; idx<RT*4; idx+=208){
        int r=idx>>2, k=idx&3; bool ok=r<nrows; int row=brow+r;
        fsm[(16+k)*RS+r] = ok ? g_agg2[(size_t)row*AGG+16+k] : 0.f;
        fsm[(36+k)*RS+r] = ok ? g_agg1[(size_t)row*AGG+16+k] : 0.f;
    }
    for (int idx=c; idx<RT; idx+=208){
        bool ok=idx<nrows; int row=brow+idx;
        fsm[56*RS+idx] = ok ? g_agg2[(size_t)row*AGG+20] : 0.f;
        fsm[57*RS+idx] = ok ? g_agg1[(size_t)row*AGG+20] : 0.f;
        sbat[idx] = ok ? batch[row] : -1;
    }
    __syncthreads();
    bool uniform = (sbat[0] == sbat[nrows-1]);
    bool fullblk = uniform && (nrows == RT);
    float lsum=0.f, lsq=0.f;
    u64 lsum2 = pack2(0.f,0.f), lsq2 = lsum2;
    float rsum=0.f, rmx=NEGINF, rmn=POSINF;
    int cur = sbat[0];
    float g58 = __ldg(&g_G[58*D1+c]);
    u64 init2 = pack2(g58, g58);
    for (int g16=0; g16<RT/16; ++g16){
        u64 acc[8];
        #pragma unroll
        for (int i=0;i<8;i++) acc[i] = init2;
        const float* fp = fsm + g16*16;
        #pragma unroll
        for (int k=0;k<58;k++){
            const ulonglong2* q = (const ulonglong2*)(fp + k*RS);
            ulonglong2 u0=q[0], u1=q[1], u2=q[2], u3=q[3];
            float wk = __ldg(&g_G[k*D1+c]);
            u64 wk2 = pack2(wk, wk);
            acc[0]=fma2(wk2,u0.x,acc[0]); acc[1]=fma2(wk2,u0.y,acc[1]);
            acc[2]=fma2(wk2,u1.x,acc[2]); acc[3]=fma2(wk2,u1.y,acc[3]);
            acc[4]=fma2(wk2,u2.x,acc[4]); acc[5]=fma2(wk2,u2.y,acc[5]);
            acc[6]=fma2(wk2,u3.x,acc[6]); acc[7]=fma2(wk2,u3.y,acc[7]);
        }
        if (fullblk){
            #pragma unroll
            for (int i=0;i<8;i++){
                lsum2 = add2(lsum2, acc[i]);
                lsq2  = fma2(acc[i], acc[i], lsq2);
                float a,b; unpack2(acc[i], a, b);
                rmx = fmaxf(rmx, fmaxf(a,b));
                rmn = fminf(rmn, fminf(a,b));
            }
        } else {
            float vals[16];
            #pragma unroll
            for (int i=0;i<8;i++) unpack2(acc[i], vals[2*i], vals[2*i+1]);
            int rb = g16*16;
            #pragma unroll
            for (int q2=0;q2<16;q2++){
                int r = rb+q2;
                if (r < nrows){
                    float v = vals[q2];
                    lsum += v; lsq = fmaf(v,v,lsq);
                    int b = sbat[r];
                    if (b != cur){
                        atomicAdd(&g_S2[cur*D1+c], rsum);
                        atomicMaxF(&g_Mx2[cur*D1+c], rmx);
                        atomicMinF(&g_Mn2[cur*D1+c], rmn);
                        rsum=0.f; rmx=NEGINF; rmn=POSINF; cur=b;
                    }
                    rsum += v; rmx = fmaxf(rmx,v); rmn = fminf(rmn,v);
                }
            }
        }
    }
    {
        float sa, sb;
        unpack2(lsum2, sa, sb); lsum += sa + sb;
        unpack2(lsq2,  sa, sb); lsq  += sa + sb;
    }
    atomicAdd(&g_S2[cur*D1+c], fullblk ? lsum : rsum);
    atomicMaxF(&g_Mx2[cur*D1+c], rmx);
    atomicMinF(&g_Mn2[cur*D1+c], rmn);
    atomicAdd(&g_sum2[c], lsum);
    atomicAdd(&g_sq2[c],  lsq);
}

// head1 = assemble (BN2 affine + pool compose, in smem) + Linear1 + PReLU
__global__ __launch_bounds__(384) void k_head1(const float* __restrict__ Wl1,
                                               const float* __restrict__ bl1,
                                               const float* __restrict__ alpha,
                                               const float* __restrict__ g2,
                                               const float* __restrict__ be2){
    extern __shared__ float sp[];   // 16*1252 floats
    __shared__ float s2s[D1], t2s[D1];
    int jc = blockIdx.x % 13, bg = blockIdx.x / 13;   // grid 52
    int t = threadIdx.x;
    for (int c=t; c<D1; c+=384){
        float m = g_sum2[c]*(1.0f/NN);
        float v = g_sq2[c]*(1.0f/NN) - m*m;
        float s = g2[c]*rsqrtf(v+EPSV);
        s2s[c] = s; t2s[c] = be2[c] - m*s;
    }
    __syncthreads();
    for (int idx=t; idx<16*416; idx+=384){
        int bb = idx/416, c = idx%416;
        int b = bg*16+bb;
        float cnt = g_cnt[b];
        float cntc = fmaxf(cnt, 1.f);
        float S, Mx, Mn, s, tt;
        if (c < D1){
            S = g_S2[b*D1+c]; Mx = g_Mx2[b*D1+c]; Mn = g_Mn2[b*D1+c];
            s = s2s[c]; tt = t2s[c];
        } else if (c < 400){
            int k = c - D1;
            S = g_S1[b*D0+k]; Mx = g_Mx1[b*D0+k]; Mn = g_Mn1[b*D0+k];
            s = g_s1[k]; tt = g_t1[k];
        } else {
            int k = c - 400;
            S = g_Sx[b*16+k]; Mx = g_Mxx[b*16+k]; Mn = 0.f;
            s = 1.f; tt = 0.f;
        }
        float sum = s*S + tt*cnt;
        float mx  = (s >= 0.f) ? s*Mx + tt : s*Mn + tt;
        float* pr = sp + bb*1252;
        pr[c]       = sum;
        pr[416 + c] = mx;
        pr[832 + c] = sum/cntc;
    }
    __syncthreads();
    int tj = t % 48, tb = t / 48;
    int j = jc*48 + tj;
    float acc0 = bl1[j], acc1 = acc0;
    const float* p0 = sp + tb*1252;
    const float* p1 = sp + (tb+8)*1252;
    #pragma unroll 4
    for (int k=0;k<1248;k++){
        float wv = Wl1[k*624+j];
        acc0 = fmaf(p0[k], wv, acc0);
        acc1 = fmaf(p1[k], wv, acc1);
    }
    float a = alpha[0];
    g_hidden[(bg*16+tb)*624 + j]   = (acc0 >= 0.f) ? acc0 : a*acc0;
    g_hidden[(bg*16+tb+8)*624 + j] = (acc1 >= 0.f) ? acc1 : a*acc1;
}

__global__ void k_head2(const float* __restrict__ Wl2, const float* __restrict__ bl2,
                        float* __restrict__ out){
    int b = blockIdx.x, l = threadIdx.x;
    float p0=0.f, p1=0.f;
    for (int k=l; k<624; k+=32){
        float h = g_hidden[b*624+k];
        p0 = fmaf(h, Wl2[k*2],   p0);
        p1 = fmaf(h, Wl2[k*2+1], p1);
    }
    #pragma unroll
    for (int o=16;o;o>>=1){
        p0 += __shfl_down_sync(0xffffffffu, p0, o);
        p1 += __shfl_down_sync(0xffffffffu, p1, o);
    }
    if (l==0){
        float a0 = p0+bl2[0], a1 = p1+bl2[1];
        float m = fmaxf(a0,a1);
        float lse = m + logf(expf(a0-m)+expf(a1-m));
        out[b*2+0] = a0-lse;
        out[b*2+1] = a1-lse;
    }
}

extern "C" void kernel_launch(void* const* d_in, const int* in_sizes, int n_in,
                              void* d_out, int out_size) {
    const float* x    = (const float*)d_in[0];
    const int*   ei   = (const int*)  d_in[1];
    const float* ea   = (const float*)d_in[2];
    const int*   batch= (const int*)  d_in[3];
    const float* Wm1  = (const float*)d_in[4];
    const float* bm1  = (const float*)d_in[5];
    const float* We1  = (const float*)d_in[6];
    const float* be1b = (const float*)d_in[7];
    const float* Ws1  = (const float*)d_in[8];
    const float* bs1  = (const float*)d_in[9];
    const float* g1   = (const float*)d_in[10];
    const float* be1  = (const float*)d_in[11];
    const float* Wm2  = (const float*)d_in[12];
    const float* bm2  = (const float*)d_in[13];
    const float* We2  = (const float*)d_in[14];
    const float* be2b = (const float*)d_in[15];
    const float* g2   = (const float*)d_in[16];
    const float* be2  = (const float*)d_in[17];
    const float* Wl1  = (const float*)d_in[18];
    const float* bl1  = (const float*)d_in[19];
    const float* alpha= (const float*)d_in[20];
    const float* Wl2  = (const float*)d_in[21];
    const float* bl2  = (const float*)d_in[22];
    const int* src = ei;
    const int* dst = ei + EE;
    float* out = (float*)d_out;

    static int init_done = 0;
    static cudaStream_t s2;
    static cudaEvent_t ev0, ev1, ev2;
    if (!init_done){
        cudaFuncSetAttribute(k_head1, cudaFuncAttributeMaxDynamicSharedMemorySize,
                             16*1252*(int)sizeof(float));
        cudaStreamCreateWithFlags(&s2, cudaStreamNonBlocking);
        cudaEventCreateWithFlags(&ev0, cudaEventDisableTiming);
        cudaEventCreateWithFlags(&ev1, cudaEventDisableTiming);
        cudaEventCreateWithFlags(&ev2, cudaEventDisableTiming);
        init_done = 1;
    }

    int gnode = (NN + RT - 1)/RT;   // 782
    cudaEventRecord(ev0, 0);
    cudaStreamWaitEvent(s2, ev0, 0);
    k_prefetch<<<148, 256, 0, s2>>>(Wl1);
    k_zero2<<<512, 256, 0, s2>>>();
    k_zero1<<<512, 256>>>();
    k_edge1<<<(EE+255)/256, 256>>>(src, dst, ea, x);
    cudaEventRecord(ev1, 0);
    cudaStreamWaitEvent(s2, ev1, 0);
    k_edge2<<<(EE+255)/256, 256, 0, s2>>>(src, dst);
    cudaEventRecord(ev2, s2);
    k_pre1<<<gnode, 192>>>(Wm1, bm1, We1, be1b, Ws1, bs1, x, batch);
    k_composeG<<<59, D1>>>(g1, be1, Wm1, We1, Ws1, bm1, be1b, bs1, Wm2, We2, bm2, be2b);
    cudaStreamWaitEvent(0, ev2, 0);   // join before k_h2 (needs agg2)
    k_h2<<<gnode, D1>>>(x, batch);
    k_head1<<<52, 384, 16*1252*(int)sizeof(float)>>>(Wl1, bl1, alpha, g2, be2);
    k_head2<<<BB, 32>>>(Wl2, bl2, out);
}